// round 1
// baseline (speedup 1.0000x reference)
#include <cuda_runtime.h>
#include <cstdint>
#include <cstddef>

#define T_DIM 256
#define B_DIM 2048
#define DIN   128
#define NQ    16
#define GN    64                    // 4 gates * 16 qubits
#define M_TOT (T_DIM * B_DIM)       // 524288 rows

// Scratch: ZX[m][gn] = x-part of z plus (b + theta).  134 MB, __device__ global
// per the no-allocation rules.
__device__ float g_zx[(size_t)M_TOT * GN];

// ---------------------------------------------------------------------------
// Phase 1: ZX = X @ Wx^T + (b + theta)
//   M = 524288, K = 128, N = 64.
//   Block: 256 threads, tile = 128 rows x 64 cols, K processed in two halves
//   of 64 so static smem is exactly 48 KB (no attribute calls needed).
//   Thread: 4 rows x 8 cols (stride-8 col mapping -> conflict-free W reads
//   thanks to XOR swizzle; X reads are per-phase broadcast LDS.128).
// ---------------------------------------------------------------------------
__global__ __launch_bounds__(256) void qlstm_p1(
    const float* __restrict__ X,
    const float* __restrict__ W,      // [4,16,144] = [gn][144]
    const float* __restrict__ Bb,     // [64]
    const float* __restrict__ Th)     // [64]
{
    __shared__ float Ws[64 * 64];     // Ws[d][col ^ (d&31)], 16 KB
    __shared__ float Xs[128 * 64];    // Xs[row][d], 32 KB

    const int tid = threadIdx.x;
    const int cg  = tid & 7;          // col group: cols cg + 8k
    const int rg  = tid >> 3;         // 0..31 : rows rg*4 + i
    const int m0  = blockIdx.x * 128;

    float acc[4][8];
#pragma unroll
    for (int i = 0; i < 4; i++)
#pragma unroll
        for (int k = 0; k < 8; k++) acc[i][k] = 0.0f;

    for (int half = 0; half < 2; ++half) {
        // --- load W half, transposed + swizzled.  gmem reads coalesced. ---
        for (int idx = tid; idx < 4096; idx += 256) {
            const int col = idx >> 6;
            const int d   = idx & 63;
            Ws[d * 64 + (col ^ (d & 31))] = W[col * 144 + half * 64 + d];
        }
        // --- load X tile half: rows m0..m0+127, d = half*64 .. +63 ---
        {
            const float4* Xg = (const float4*)(X + (size_t)m0 * DIN + half * 64);
            float4* Xs4 = (float4*)Xs;
            for (int idx = tid; idx < 128 * 16; idx += 256) {
                const int row = idx >> 4;
                const int dq  = idx & 15;
                Xs4[row * 16 + dq] = Xg[(size_t)row * 32 + dq];
            }
        }
        __syncthreads();

#pragma unroll 2
        for (int d4 = 0; d4 < 64; d4 += 4) {
            float4 xv[4];
#pragma unroll
            for (int i = 0; i < 4; i++)
                xv[i] = *(const float4*)&Xs[(rg * 4 + i) * 64 + d4];
#pragma unroll
            for (int dd = 0; dd < 4; dd++) {
                const int d  = d4 + dd;
                const int sx = d & 31;
                float wv[8];
#pragma unroll
                for (int k = 0; k < 8; k++)
                    wv[k] = Ws[d * 64 + ((cg + 8 * k) ^ sx)];
#pragma unroll
                for (int i = 0; i < 4; i++) {
                    const float xs = (&xv[i].x)[dd];
#pragma unroll
                    for (int k = 0; k < 8; k++)
                        acc[i][k] = fmaf(xs, wv[k], acc[i][k]);
                }
            }
        }
        __syncthreads();
    }

    // bias + theta folded here; store
    float bt[8];
#pragma unroll
    for (int k = 0; k < 8; k++) {
        const int col = cg + 8 * k;
        bt[k] = Bb[col] + Th[col];
    }
#pragma unroll
    for (int i = 0; i < 4; i++) {
        const size_t row = (size_t)m0 + rg * 4 + i;
#pragma unroll
        for (int k = 0; k < 8; k++)
            g_zx[row * GN + cg + 8 * k] = acc[i][k] + bt[k];
    }
}

// ---------------------------------------------------------------------------
// Phase 2: sequential recurrence.  16 threads per batch element, 8 elements
// per 128-thread block.  Lane n owns h[n], c[n], Wh[4][16] in registers.
// h broadcast via double-buffered smem; cumprod via shfl scan (width 16).
// ---------------------------------------------------------------------------
__device__ __forceinline__ float sigf(float x) {
    return __fdividef(1.0f, 1.0f + __expf(-x));
}
__device__ __forceinline__ float tanh_fast(float x) {
    // tanh(x) = 1 - 2/(e^{2x}+1); exact limits at +/-inf
    return 1.0f - __fdividef(2.0f, __expf(2.0f * x) + 1.0f);
}

__global__ __launch_bounds__(128) void qlstm_p2(
    const float* __restrict__ W,      // [gn][144]; Wh at d = 128..143
    float* __restrict__ out,
    const int write_final)
{
    __shared__ float hs[2][8][16];

    const int tid = threadIdx.x;
    const int le  = tid >> 4;         // local element 0..7
    const int n   = tid & 15;         // qubit index
    const int e   = blockIdx.x * 8 + le;

    // Wh[g][j] = W[(g*16+n)*144 + 128 + j]
    float Wh[4][16];
#pragma unroll
    for (int g = 0; g < 4; g++) {
        const float* wp = W + (size_t)(g * 16 + n) * 144 + 128;
#pragma unroll
        for (int j = 0; j < 16; j++) Wh[g][j] = wp[j];
    }

    float c = 0.0f, h = 0.0f;
    hs[0][le][n] = 0.0f;
    __syncthreads();

    const size_t stepStride = (size_t)B_DIM * GN;
    const float* zp = g_zx + (size_t)e * GN + n;

    float zc[4];
#pragma unroll
    for (int g = 0; g < 4; g++) zc[g] = zp[g * 16];

    float* outp = out + (size_t)e * NQ + n;

    for (int t = 0; t < T_DIM; t++) {
        // prefetch next step's zx (off the critical chain)
        float zn[4] = {0.f, 0.f, 0.f, 0.f};
        if (t + 1 < T_DIM) {
            const float* zq = zp + (size_t)(t + 1) * stepStride;
#pragma unroll
            for (int g = 0; g < 4; g++) zn[g] = zq[g * 16];
        }

        // read h vector (broadcast from smem, 4x LDS.128)
        const int buf = t & 1;
        float hv[16];
        {
            const float4* hp = (const float4*)hs[buf][le];
#pragma unroll
            for (int q = 0; q < 4; q++) {
                const float4 v = hp[q];
                hv[4 * q + 0] = v.x; hv[4 * q + 1] = v.y;
                hv[4 * q + 2] = v.z; hv[4 * q + 3] = v.w;
            }
        }

        float z0 = zc[0], z1 = zc[1], z2 = zc[2], z3 = zc[3];
#pragma unroll
        for (int j = 0; j < 16; j++) {
            const float hj = hv[j];
            z0 = fmaf(hj, Wh[0][j], z0);
            z1 = fmaf(hj, Wh[1][j], z1);
            z2 = fmaf(hj, Wh[2][j], z2);
            z3 = fmaf(hj, Wh[3][j], z3);
        }

        float p0 = __cosf(z0), p1 = __cosf(z1), p2 = __cosf(z2), p3 = __cosf(z3);
        // inclusive prefix product across the 16-lane segment
#pragma unroll
        for (int off = 1; off < 16; off <<= 1) {
            const float v0 = __shfl_up_sync(0xffffffffu, p0, off, 16);
            const float v1 = __shfl_up_sync(0xffffffffu, p1, off, 16);
            const float v2 = __shfl_up_sync(0xffffffffu, p2, off, 16);
            const float v3 = __shfl_up_sync(0xffffffffu, p3, off, 16);
            if (n >= off) { p0 *= v0; p1 *= v1; p2 *= v2; p3 *= v3; }
        }

        const float f  = sigf(p0);
        const float ii = sigf(p1);
        const float gg = tanh_fast(p2);
        const float o  = sigf(p3);
        c = fmaf(f, c, ii * gg);
        h = o * tanh_fast(c);

        outp[(size_t)t * (B_DIM * NQ)] = h;
        hs[buf ^ 1][le][n] = h;
        __syncthreads();

        zc[0] = zn[0]; zc[1] = zn[1]; zc[2] = zn[2]; zc[3] = zn[3];
    }

    if (write_final) {
        float* hx = out + (size_t)T_DIM * B_DIM * NQ;
        hx[(size_t)e * NQ + n] = h;                       // hx
        hx[(size_t)B_DIM * NQ + (size_t)e * NQ + n] = c;  // cx
    }
}

// ---------------------------------------------------------------------------
extern "C" void kernel_launch(void* const* d_in, const int* in_sizes, int n_in,
                              void* d_out, int out_size) {
    const float* X  = (const float*)d_in[0];   // inputs [T,B,DIN]
    const float* W  = (const float*)d_in[1];   // [4,16,144]
    const float* Bb = (const float*)d_in[2];   // [4,16]
    const float* Th = (const float*)d_in[3];   // [4,16]
    float* out = (float*)d_out;

    qlstm_p1<<<M_TOT / 128, 256>>>(X, W, Bb, Th);

    const int need = T_DIM * B_DIM * NQ + 2 * B_DIM * NQ;
    const int wf = (out_size >= need) ? 1 : 0;
    qlstm_p2<<<B_DIM / 8, 128>>>(W, out, wf);
}

// round 2
// speedup vs baseline: 1.0223x; 1.0223x over previous
#include <cuda_runtime.h>
#include <cstdint>
#include <cstddef>

#define T_DIM 256
#define B_DIM 2048
#define DIN   128
#define NQ    16
#define GN    64
#define M_TOT (T_DIM * B_DIM)

// Scratch ZX[m][gn] — __device__ global per no-allocation rules (134 MB).
__device__ float g_zx[(size_t)M_TOT * GN];

// Packed fp32x2 FMA (sm_100+): d = a*b + c on 2 lanes per instruction.
#define FMA_F32X2(d, a, b, c) \
    asm("fma.rn.f32x2 %0, %1, %2, %3;" : "=l"(d) : "l"(a), "l"(b), "l"(c))
#define PACK_DUP(xx, xs) \
    asm("mov.b64 %0, {%1, %1};" : "=l"(xx) : "f"(xs))
#define UNPACK2(lo, hi, v) \
    asm("mov.b64 {%0, %1}, %2;" : "=f"(lo), "=f"(hi) : "l"(v))

// ---------------------------------------------------------------------------
// Phase 1: ZX = X @ Wx^T + (b + theta),  M=524288, K=128, N=64.
// 256 threads / block, tile 128 rows x 64 cols, K in two halves of 64
// (static smem exactly 48 KB). Thread: 4 rows x 8 CONTIGUOUS cols, packed
// as 4 col-pairs -> 16 FFMA2 per d instead of 32 FFMA.
// Ws[d][col ^ 8*(d&7)]: XOR by multiples of 8 keeps each thread's 8 cols
// contiguous (conflict-free 2x LDS.128) while spreading store banks.
// ---------------------------------------------------------------------------
__global__ __launch_bounds__(256) void qlstm_p1(
    const float* __restrict__ X,
    const float* __restrict__ W,      // [64][144]
    const float* __restrict__ Bb,     // [64]
    const float* __restrict__ Th)     // [64]
{
    __shared__ float Ws[64 * 64];     // 16 KB
    __shared__ float Xs[128 * 64];    // 32 KB

    const int tid = threadIdx.x;
    const int cg  = tid & 7;          // cols cg*8 .. cg*8+7
    const int rg  = tid >> 3;         // rows rg*4 .. rg*4+3
    const int m0  = blockIdx.x * 128;

    unsigned long long acc[4][4];
#pragma unroll
    for (int i = 0; i < 4; i++)
#pragma unroll
        for (int k = 0; k < 4; k++) acc[i][k] = 0ULL;

    for (int half = 0; half < 2; ++half) {
        for (int idx = tid; idx < 4096; idx += 256) {
            const int col = idx >> 6;
            const int d   = idx & 63;
            Ws[d * 64 + (col ^ ((d & 7) * 8))] = W[col * 144 + half * 64 + d];
        }
        {
            const float4* Xg = (const float4*)(X + (size_t)m0 * DIN + half * 64);
            float4* Xs4 = (float4*)Xs;
            for (int idx = tid; idx < 128 * 16; idx += 256) {
                const int row = idx >> 4;
                const int dq  = idx & 15;
                Xs4[row * 16 + dq] = Xg[(size_t)row * 32 + dq];
            }
        }
        __syncthreads();

#pragma unroll 2
        for (int d4 = 0; d4 < 64; d4 += 4) {
            float4 xv[4];
#pragma unroll
            for (int i = 0; i < 4; i++)
                xv[i] = *(const float4*)&Xs[(rg * 4 + i) * 64 + d4];
#pragma unroll
            for (int dd = 0; dd < 4; dd++) {
                const int d  = d4 + dd;
                const int sw = d * 64 + ((cg * 8) ^ ((d & 7) * 8));
                const ulonglong2 wa = *(const ulonglong2*)&Ws[sw];
                const ulonglong2 wb = *(const ulonglong2*)&Ws[sw + 4];
#pragma unroll
                for (int i = 0; i < 4; i++) {
                    const float xs = (&xv[i].x)[dd];
                    unsigned long long xx;
                    PACK_DUP(xx, xs);
                    FMA_F32X2(acc[i][0], xx, wa.x, acc[i][0]);
                    FMA_F32X2(acc[i][1], xx, wa.y, acc[i][1]);
                    FMA_F32X2(acc[i][2], xx, wb.x, acc[i][2]);
                    FMA_F32X2(acc[i][3], xx, wb.y, acc[i][3]);
                }
            }
        }
        __syncthreads();
    }

    // epilogue: unpack, add (b + theta), 2x STG.128 per row
    float bt[8];
#pragma unroll
    for (int k = 0; k < 8; k++) bt[k] = Bb[cg * 8 + k] + Th[cg * 8 + k];

#pragma unroll
    for (int i = 0; i < 4; i++) {
        float v[8];
#pragma unroll
        for (int k = 0; k < 4; k++)
            UNPACK2(v[2 * k], v[2 * k + 1], acc[i][k]);
#pragma unroll
        for (int k = 0; k < 8; k++) v[k] += bt[k];
        const size_t row = (size_t)m0 + rg * 4 + i;
        float4* op = (float4*)(g_zx + row * GN + cg * 8);
        op[0] = make_float4(v[0], v[1], v[2], v[3]);
        op[1] = make_float4(v[4], v[5], v[6], v[7]);
    }
}

// ---------------------------------------------------------------------------
// Phase 2: recurrence. 16 lanes per batch element, no block-level sync:
// h broadcast via __shfl_sync(width=16). ZX prefetched 3 steps ahead
// (ring z0/z1/z2) so DRAM latency is pipelined, not serialized per step.
// ---------------------------------------------------------------------------
__device__ __forceinline__ float sigf(float x) {
    return __fdividef(1.0f, 1.0f + __expf(-x));
}
__device__ __forceinline__ float tanh_fast(float x) {
    return 1.0f - __fdividef(2.0f, __expf(2.0f * x) + 1.0f);
}

__global__ __launch_bounds__(128) void qlstm_p2(
    const float* __restrict__ W,      // [gn][144]; Wh at d = 128..143
    float* __restrict__ out,
    const int write_final)
{
    const int tid = threadIdx.x;
    const int n   = tid & 15;
    const int e   = blockIdx.x * 8 + (tid >> 4);

    float Wh[4][16];
#pragma unroll
    for (int g = 0; g < 4; g++) {
        const float* wp = W + (size_t)(g * 16 + n) * 144 + 128;
#pragma unroll
        for (int j = 0; j < 16; j++) Wh[g][j] = wp[j];
    }

    float c = 0.0f, h = 0.0f;

    const size_t stepStride = (size_t)B_DIM * GN;
    const float* zp = g_zx + (size_t)e * GN + n;
    float* outp = out + (size_t)e * NQ + n;

    // prefetch ring, depth 3
    float z0[4], z1[4], z2[4];
#pragma unroll
    for (int g = 0; g < 4; g++) {
        z0[g] = zp[g * 16];
        z1[g] = zp[stepStride + g * 16];
        z2[g] = zp[2 * stepStride + g * 16];
    }

    for (int t = 0; t < T_DIM; t++) {
        // broadcast h of this element's 16 lanes
        float hv[16];
#pragma unroll
        for (int j = 0; j < 16; j++)
            hv[j] = __shfl_sync(0xffffffffu, h, j, 16);

        float z[4];
#pragma unroll
        for (int g = 0; g < 4; g++) {
            float s0 = z0[g], s1 = 0.0f, s2 = 0.0f, s3 = 0.0f;
#pragma unroll
            for (int j = 0; j < 4; j++) {
                s0 = fmaf(hv[j],      Wh[g][j],      s0);
                s1 = fmaf(hv[j + 4],  Wh[g][j + 4],  s1);
                s2 = fmaf(hv[j + 8],  Wh[g][j + 8],  s2);
                s3 = fmaf(hv[j + 12], Wh[g][j + 12], s3);
            }
            z[g] = (s0 + s1) + (s2 + s3);
        }

        // rotate ring + issue next load (t+3) early, off the critical chain
#pragma unroll
        for (int g = 0; g < 4; g++) { z0[g] = z1[g]; z1[g] = z2[g]; }
        if (t + 3 < T_DIM) {
            const float* zq = zp + (size_t)(t + 3) * stepStride;
#pragma unroll
            for (int g = 0; g < 4; g++) z2[g] = zq[g * 16];
        }

        float p0 = __cosf(z[0]), p1 = __cosf(z[1]);
        float p2 = __cosf(z[2]), p3 = __cosf(z[3]);
#pragma unroll
        for (int off = 1; off < 16; off <<= 1) {
            const float v0 = __shfl_up_sync(0xffffffffu, p0, off, 16);
            const float v1 = __shfl_up_sync(0xffffffffu, p1, off, 16);
            const float v2 = __shfl_up_sync(0xffffffffu, p2, off, 16);
            const float v3 = __shfl_up_sync(0xffffffffu, p3, off, 16);
            if (n >= off) { p0 *= v0; p1 *= v1; p2 *= v2; p3 *= v3; }
        }

        const float f  = sigf(p0);
        const float ii = sigf(p1);
        const float gg = tanh_fast(p2);
        const float o  = sigf(p3);
        c = fmaf(f, c, ii * gg);
        h = o * tanh_fast(c);

        outp[(size_t)t * (B_DIM * NQ)] = h;
    }

    if (write_final) {
        float* hx = out + (size_t)T_DIM * B_DIM * NQ;
        hx[(size_t)e * NQ + n] = h;
        hx[(size_t)B_DIM * NQ + (size_t)e * NQ + n] = c;
    }
}

// ---------------------------------------------------------------------------
extern "C" void kernel_launch(void* const* d_in, const int* in_sizes, int n_in,
                              void* d_out, int out_size) {
    const float* X  = (const float*)d_in[0];
    const float* W  = (const float*)d_in[1];
    const float* Bb = (const float*)d_in[2];
    const float* Th = (const float*)d_in[3];
    float* out = (float*)d_out;

    qlstm_p1<<<M_TOT / 128, 256>>>(X, W, Bb, Th);

    const int need = T_DIM * B_DIM * NQ + 2 * B_DIM * NQ;
    const int wf = (out_size >= need) ? 1 : 0;
    qlstm_p2<<<B_DIM / 8, 128>>>(W, out, wf);
}

// round 4
// speedup vs baseline: 1.5529x; 1.5191x over previous
#include <cuda_runtime.h>
#include <cstdint>
#include <cstddef>

#define T_DIM 256
#define B_DIM 2048
#define DIN   128
#define NQ    16
#define GN    64
#define M_TOT (T_DIM * B_DIM)

// ZX scratch padded by 4 timesteps so phase-2 prefetch needs no bounds check.
__device__ __align__(256) float g_zx[(size_t)(T_DIM + 4) * B_DIM * GN];

// ===========================================================================
// Phase 1: ZX = X @ Wx^T + (b+theta) via portable mma.sync m16n8k8 tf32,
// 3xTF32 split for fp32-grade accuracy.
//   Block: 256 threads / 8 warps; warp computes 32 rows x 64 cols.
//   Block tile: 256 rows. K = 128 in 4 chunks of 32.
//   SMEM: (hi,lo) tf32 pairs packed as uint2; row stride 36 float2 so
//   fragment LDS.64 bank index = 4g+tig (conflict-free per 16-lane phase).
// ===========================================================================
#define SROW 36                         // float2 stride per row
#define WS_OFF   256                    // bytes: bias table first
#define XS_OFF   (WS_OFF + 64 * SROW * 8)
#define P1_SMEM  (XS_OFF + 256 * SROW * 8)   // 256 + 18432 + 73728 = 92416

__device__ __forceinline__ uint32_t tf32_hi(float x) {
    uint32_t r; asm("cvt.rna.tf32.f32 %0, %1;" : "=r"(r) : "f"(x)); return r;
}
__device__ __forceinline__ uint2 tf32_split(float v) {
    uint2 u;
    u.x = tf32_hi(v);
    u.y = tf32_hi(v - __uint_as_float(u.x));
    return u;
}
// d += A(tf32) * B(tf32), m16n8k8
#define MMA_TF32(c, a0, a1, a2, a3, b0, b1) \
    asm volatile("mma.sync.aligned.m16n8k8.row.col.f32.tf32.tf32.f32 " \
        "{%0,%1,%2,%3}, {%4,%5,%6,%7}, {%8,%9}, {%0,%1,%2,%3};" \
        : "+f"((c)[0]), "+f"((c)[1]), "+f"((c)[2]), "+f"((c)[3]) \
        : "r"(a0), "r"(a1), "r"(a2), "r"(a3), "r"(b0), "r"(b1))

__global__ __launch_bounds__(256) void qlstm_p1(
    const float* __restrict__ X,
    const float* __restrict__ W,      // [64][144]
    const float* __restrict__ Bb,
    const float* __restrict__ Th)
{
    extern __shared__ char smem[];
    float* bts = (float*)smem;                 // 64 floats
    uint2* Ws2 = (uint2*)(smem + WS_OFF);      // [n=64][k=36]
    uint2* Xs2 = (uint2*)(smem + XS_OFF);      // [row=256][k=36]

    const int tid  = threadIdx.x;
    const int lane = tid & 31, w = tid >> 5;
    const int g = lane >> 2, tig = lane & 3;
    const int rb = w * 32;
    const size_t m0 = (size_t)blockIdx.x * 256;

    if (tid < 64) bts[tid] = Bb[tid] + Th[tid];

    // staging index maps (fixed per thread)
    const int xr_r = tid >> 3, xr_q = tid & 7;       // X: 8 chunks of 256
    const int wr_n0 = tid >> 3, wr_q = tid & 7;      // W: 2 chunks of 256

    float C[2][8][4];
#pragma unroll
    for (int s = 0; s < 2; s++)
#pragma unroll
        for (int nt = 0; nt < 8; nt++)
#pragma unroll
            for (int q = 0; q < 4; q++) C[s][nt][q] = 0.0f;

    // prefetch chunk 0
    float4 xr[8], wr[2];
#pragma unroll
    for (int i = 0; i < 8; i++)
        xr[i] = *(const float4*)(X + (m0 + xr_r + 32 * i) * DIN + 4 * xr_q);
#pragma unroll
    for (int i = 0; i < 2; i++)
        wr[i] = *(const float4*)(W + (wr_n0 + 32 * i) * 144 + 4 * wr_q);

    for (int kc = 0; kc < 4; kc++) {
        // ---- store staged registers (split to tf32 hi/lo pairs) ----
#pragma unroll
        for (int i = 0; i < 8; i++) {
            const uint2 u0 = tf32_split(xr[i].x), u1 = tf32_split(xr[i].y);
            const uint2 u2 = tf32_split(xr[i].z), u3 = tf32_split(xr[i].w);
            uint2* p = &Xs2[(xr_r + 32 * i) * SROW + 4 * xr_q];
            *(uint4*)(p)     = make_uint4(u0.x, u0.y, u1.x, u1.y);
            *(uint4*)(p + 2) = make_uint4(u2.x, u2.y, u3.x, u3.y);
        }
#pragma unroll
        for (int i = 0; i < 2; i++) {
            const uint2 u0 = tf32_split(wr[i].x), u1 = tf32_split(wr[i].y);
            const uint2 u2 = tf32_split(wr[i].z), u3 = tf32_split(wr[i].w);
            uint2* p = &Ws2[(wr_n0 + 32 * i) * SROW + 4 * wr_q];
            *(uint4*)(p)     = make_uint4(u0.x, u0.y, u1.x, u1.y);
            *(uint4*)(p + 2) = make_uint4(u2.x, u2.y, u3.x, u3.y);
        }
        __syncthreads();

        // ---- prefetch next chunk (overlaps with compute below) ----
        if (kc < 3) {
            const int kb = (kc + 1) * 32;
#pragma unroll
            for (int i = 0; i < 8; i++)
                xr[i] = *(const float4*)(X + (m0 + xr_r + 32 * i) * DIN + kb + 4 * xr_q);
#pragma unroll
            for (int i = 0; i < 2; i++)
                wr[i] = *(const float4*)(W + (wr_n0 + 32 * i) * 144 + kb + 4 * wr_q);
        }

        // ---- compute: 4 ksteps x 8 ntiles x 6 mma ----
#pragma unroll
        for (int ks = 0; ks < 4; ks++) {
            const int ka = ks * 8 + tig;
            const uint2 a0 = Xs2[(rb + g) * SROW + ka];
            const uint2 a2 = Xs2[(rb + g) * SROW + ka + 4];
            const uint2 a1 = Xs2[(rb + g + 8) * SROW + ka];
            const uint2 a3 = Xs2[(rb + g + 8) * SROW + ka + 4];
            const uint2 c0 = Xs2[(rb + 16 + g) * SROW + ka];
            const uint2 c2 = Xs2[(rb + 16 + g) * SROW + ka + 4];
            const uint2 c1 = Xs2[(rb + 24 + g) * SROW + ka];
            const uint2 c3 = Xs2[(rb + 24 + g) * SROW + ka + 4];
#pragma unroll
            for (int nt = 0; nt < 8; nt++) {
                const uint2 b0 = Ws2[(nt * 8 + g) * SROW + ka];
                const uint2 b1 = Ws2[(nt * 8 + g) * SROW + ka + 4];
                MMA_TF32(C[0][nt], a0.x, a1.x, a2.x, a3.x, b0.x, b1.x);
                MMA_TF32(C[0][nt], a0.y, a1.y, a2.y, a3.y, b0.x, b1.x);
                MMA_TF32(C[0][nt], a0.x, a1.x, a2.x, a3.x, b0.y, b1.y);
                MMA_TF32(C[1][nt], c0.x, c1.x, c2.x, c3.x, b0.x, b1.x);
                MMA_TF32(C[1][nt], c0.y, c1.y, c2.y, c3.y, b0.x, b1.x);
                MMA_TF32(C[1][nt], c0.x, c1.x, c2.x, c3.x, b0.y, b1.y);
            }
        }
        __syncthreads();
    }

    // ---- epilogue: add (b+theta), write pairs ----
    float2 bt2[8];
#pragma unroll
    for (int nt = 0; nt < 8; nt++)
        bt2[nt] = *(const float2*)&bts[nt * 8 + 2 * tig];

#pragma unroll
    for (int s = 0; s < 2; s++) {
        const size_t r0 = m0 + rb + 16 * s + g;
#pragma unroll
        for (int nt = 0; nt < 8; nt++) {
            const int col = nt * 8 + 2 * tig;
            *(float2*)&g_zx[r0 * GN + col] =
                make_float2(C[s][nt][0] + bt2[nt].x, C[s][nt][1] + bt2[nt].y);
            *(float2*)&g_zx[(r0 + 8) * GN + col] =
                make_float2(C[s][nt][2] + bt2[nt].x, C[s][nt][3] + bt2[nt].y);
        }
    }
}

// ===========================================================================
// Phase 2: recurrence. 16 lanes/element; h via per-group smem double buffer
// (1 syncwarp/step); cumprod via radix-4 scan (2 shfl rounds); t unrolled x4
// with 4-step batched prefetch (distance 4..7 steps into padded g_zx).
// ===========================================================================
__device__ __forceinline__ float sigf(float x) {
    return __fdividef(1.0f, 1.0f + __expf(-x));
}
__device__ __forceinline__ float tanh_fast(float x) {
    return 1.0f - __fdividef(2.0f, __expf(2.0f * x) + 1.0f);
}
__device__ __forceinline__ float scanp(float p, int n) {
    float v1 = __shfl_up_sync(0xffffffffu, p, 1, 16);
    float v2 = __shfl_up_sync(0xffffffffu, p, 2, 16);
    float v3 = __shfl_up_sync(0xffffffffu, p, 3, 16);
    float m = ((n >= 1) ? v1 : 1.0f) * ((n >= 2) ? v2 : 1.0f);
    p *= m * ((n >= 3) ? v3 : 1.0f);
    float w1 = __shfl_up_sync(0xffffffffu, p, 4, 16);
    float w2 = __shfl_up_sync(0xffffffffu, p, 8, 16);
    float w3 = __shfl_up_sync(0xffffffffu, p, 12, 16);
    float mm = ((n >= 4) ? w1 : 1.0f) * ((n >= 8) ? w2 : 1.0f);
    return p * (mm * ((n >= 12) ? w3 : 1.0f));
}

__global__ __launch_bounds__(128) void qlstm_p2(
    const float* __restrict__ W, float* __restrict__ out, const int write_final)
{
    __shared__ float hs[2][8][16];

    const int tid = threadIdx.x;
    const int n   = tid & 15;
    const int grp = tid >> 4;
    const int e   = blockIdx.x * 8 + grp;

    float Wh[4][16];
#pragma unroll
    for (int g = 0; g < 4; g++) {
        const float* wp = W + (size_t)(g * 16 + n) * 144 + 128;
#pragma unroll
        for (int j = 0; j < 16; j++) Wh[g][j] = wp[j];
    }

    float c = 0.0f, h = 0.0f;
    hs[0][grp][n] = 0.0f;
    __syncwarp();

    const size_t SS = (size_t)B_DIM * GN;
    const float* zp = g_zx + (size_t)e * GN + n;
    float* outp = out + (size_t)e * NQ + n;

    float zc[4][4];
#pragma unroll
    for (int s = 0; s < 4; s++)
#pragma unroll
        for (int g = 0; g < 4; g++) zc[s][g] = zp[s * SS + g * 16];
    zp += 4 * SS;

    for (int tb = 0; tb < 64; ++tb) {
        float zn[4][4];
#pragma unroll
        for (int s = 0; s < 4; s++)
#pragma unroll
            for (int g = 0; g < 4; g++) zn[s][g] = zp[s * SS + g * 16];
        zp += 4 * SS;

#pragma unroll
        for (int s = 0; s < 4; s++) {
            float hv[16];
            {
                const float4* hp = (const float4*)hs[s & 1][grp];
#pragma unroll
                for (int q = 0; q < 4; q++) {
                    const float4 v = hp[q];
                    hv[4 * q + 0] = v.x; hv[4 * q + 1] = v.y;
                    hv[4 * q + 2] = v.z; hv[4 * q + 3] = v.w;
                }
            }
            float z[4];
#pragma unroll
            for (int g = 0; g < 4; g++) {
                float s0 = zc[s][g], s1 = 0.0f, s2 = 0.0f, s3 = 0.0f;
#pragma unroll
                for (int j = 0; j < 4; j++) {
                    s0 = fmaf(hv[j],      Wh[g][j],      s0);
                    s1 = fmaf(hv[j + 4],  Wh[g][j + 4],  s1);
                    s2 = fmaf(hv[j + 8],  Wh[g][j + 8],  s2);
                    s3 = fmaf(hv[j + 12], Wh[g][j + 12], s3);
                }
                z[g] = (s0 + s1) + (s2 + s3);
            }

            const float q0 = scanp(__cosf(z[0]), n);
            const float q1 = scanp(__cosf(z[1]), n);
            const float q2 = scanp(__cosf(z[2]), n);
            const float q3 = scanp(__cosf(z[3]), n);

            const float f  = sigf(q0);
            const float ii = sigf(q1);
            const float gg = tanh_fast(q2);
            const float o  = sigf(q3);
            c = fmaf(f, c, ii * gg);
            h = o * tanh_fast(c);

            outp[0] = h;
            outp += B_DIM * NQ;
            hs[(s + 1) & 1][grp][n] = h;
            __syncwarp();
        }
#pragma unroll
        for (int s = 0; s < 4; s++)
#pragma unroll
            for (int g = 0; g < 4; g++) zc[s][g] = zn[s][g];
    }

    if (write_final) {
        float* hx = out + (size_t)T_DIM * B_DIM * NQ;
        hx[(size_t)e * NQ + n] = h;
        hx[(size_t)B_DIM * NQ + (size_t)e * NQ + n] = c;
    }
}

// ---------------------------------------------------------------------------
extern "C" void kernel_launch(void* const* d_in, const int* in_sizes, int n_in,
                              void* d_out, int out_size) {
    const float* X  = (const float*)d_in[0];
    const float* W  = (const float*)d_in[1];
    const float* Bb = (const float*)d_in[2];
    const float* Th = (const float*)d_in[3];
    float* out = (float*)d_out;

    static int smem_set = 0;
    if (!smem_set) {
        cudaFuncSetAttribute(qlstm_p1, cudaFuncAttributeMaxDynamicSharedMemorySize,
                             P1_SMEM);
        smem_set = 1;
    }
    qlstm_p1<<<M_TOT / 256, 256, P1_SMEM>>>(X, W, Bb, Th);

    const int need = T_DIM * B_DIM * NQ + 2 * B_DIM * NQ;
    const int wf = (out_size >= need) ? 1 : 0;
    qlstm_p2<<<B_DIM / 8, 128>>>(W, out, wf);
}

// round 5
// speedup vs baseline: 2.0915x; 1.3469x over previous
#include <cuda_runtime.h>
#include <cstdint>
#include <cstddef>

#define T_DIM 256
#define B_DIM 2048
#define DIN   128
#define NQ    16
#define GN    64
#define M_TOT (T_DIM * B_DIM)

// ZX scratch padded by 4 timesteps so phase-2 prefetch needs no bounds check.
__device__ __align__(256) float g_zx[(size_t)(T_DIM + 4) * B_DIM * GN];

// ===========================================================================
// Phase 1: ZX = X @ Wx^T + (b+theta) via mma.sync m16n8k16 bf16, 3xBF16 split.
//   Block: 256 threads / 8 warps; warp tile 32 rows x 64 cols; block 256 rows.
//   K = 128 in 4 chunks of 32. SMEM holds (hi,lo) bf16x2 pairs as uint2 per
//   (row, kpair); row stride 20 uint2 (20 mod 16 == 4 -> fragment LDS.64
//   bank-pair = 4g+tig+const, conflict-free).
// ===========================================================================
#define SROW8 20                          // uint2 per row
#define WS_OFF 256
#define XS_OFF (WS_OFF + 64 * SROW8 * 8)      // 10496
#define P1_SMEM (XS_OFF + 256 * SROW8 * 8)    // 51456

__device__ __forceinline__ uint2 bf16_split2(float x, float y) {
    uint32_t h, l;
    asm("cvt.rn.bf16x2.f32 %0, %1, %2;" : "=r"(h) : "f"(y), "f"(x));
    const float hx = __uint_as_float(h << 16);
    const float hy = __uint_as_float(h & 0xffff0000u);
    const float lx = x - hx, ly = y - hy;
    asm("cvt.rn.bf16x2.f32 %0, %1, %2;" : "=r"(l) : "f"(ly), "f"(lx));
    return make_uint2(h, l);
}

#define MMA_BF16(c, a0, a1, a2, a3, b0, b1) \
    asm volatile("mma.sync.aligned.m16n8k16.row.col.f32.bf16.bf16.f32 " \
        "{%0,%1,%2,%3}, {%4,%5,%6,%7}, {%8,%9}, {%0,%1,%2,%3};" \
        : "+f"((c)[0]), "+f"((c)[1]), "+f"((c)[2]), "+f"((c)[3]) \
        : "r"(a0), "r"(a1), "r"(a2), "r"(a3), "r"(b0), "r"(b1))

__global__ __launch_bounds__(256, 2) void qlstm_p1(
    const float* __restrict__ X,
    const float* __restrict__ W,      // [64][144]
    const float* __restrict__ Bb,
    const float* __restrict__ Th)
{
    extern __shared__ char smem[];
    float* bts = (float*)smem;
    uint2* Ws2 = (uint2*)(smem + WS_OFF);   // [n=64][kp], stride 20
    uint2* Xs2 = (uint2*)(smem + XS_OFF);   // [row=256][kp], stride 20

    const int tid  = threadIdx.x;
    const int lane = tid & 31, w = tid >> 5;
    const int g = lane >> 2, tig = lane & 3;
    const int rb = w * 32;
    const size_t m0 = (size_t)blockIdx.x * 256;

    if (tid < 64) bts[tid] = Bb[tid] + Th[tid];

    const int sr = tid >> 3, sq = tid & 7;   // staging: row-in-32, float4 idx

    float C[2][8][4];
#pragma unroll
    for (int s = 0; s < 2; s++)
#pragma unroll
        for (int nt = 0; nt < 8; nt++)
#pragma unroll
            for (int q = 0; q < 4; q++) C[s][nt][q] = 0.0f;

    // prefetch chunk 0
    float4 xr[8], wr[2];
#pragma unroll
    for (int i = 0; i < 8; i++)
        xr[i] = *(const float4*)(X + (m0 + sr + 32 * i) * DIN + 4 * sq);
#pragma unroll
    for (int i = 0; i < 2; i++)
        wr[i] = *(const float4*)(W + (sr + 32 * i) * 144 + 4 * sq);

    for (int kc = 0; kc < 4; kc++) {
        // ---- store staged registers, split hi/lo bf16x2 ----
#pragma unroll
        for (int i = 0; i < 8; i++) {
            const uint2 u0 = bf16_split2(xr[i].x, xr[i].y);
            const uint2 u1 = bf16_split2(xr[i].z, xr[i].w);
            *(uint4*)&Xs2[(sr + 32 * i) * SROW8 + 2 * sq] =
                make_uint4(u0.x, u0.y, u1.x, u1.y);
        }
#pragma unroll
        for (int i = 0; i < 2; i++) {
            const uint2 u0 = bf16_split2(wr[i].x, wr[i].y);
            const uint2 u1 = bf16_split2(wr[i].z, wr[i].w);
            *(uint4*)&Ws2[(sr + 32 * i) * SROW8 + 2 * sq] =
                make_uint4(u0.x, u0.y, u1.x, u1.y);
        }
        __syncthreads();

        // ---- prefetch next chunk (overlaps compute) ----
        if (kc < 3) {
            const int kb = (kc + 1) * 32;
#pragma unroll
            for (int i = 0; i < 8; i++)
                xr[i] = *(const float4*)(X + (m0 + sr + 32 * i) * DIN + kb + 4 * sq);
#pragma unroll
            for (int i = 0; i < 2; i++)
                wr[i] = *(const float4*)(W + (sr + 32 * i) * 144 + kb + 4 * sq);
        }

        // ---- compute: 2 ksteps (k16) x 8 ntiles x 6 mma ----
#pragma unroll
        for (int ks = 0; ks < 2; ks++) {
            const int kp = ks * 8 + tig;
            const uint2 A0 = Xs2[(rb + g) * SROW8 + kp];
            const uint2 A1 = Xs2[(rb + 8 + g) * SROW8 + kp];
            const uint2 A2 = Xs2[(rb + g) * SROW8 + kp + 4];
            const uint2 A3 = Xs2[(rb + 8 + g) * SROW8 + kp + 4];
            const uint2 D0 = Xs2[(rb + 16 + g) * SROW8 + kp];
            const uint2 D1 = Xs2[(rb + 24 + g) * SROW8 + kp];
            const uint2 D2 = Xs2[(rb + 16 + g) * SROW8 + kp + 4];
            const uint2 D3 = Xs2[(rb + 24 + g) * SROW8 + kp + 4];
#pragma unroll
            for (int nt = 0; nt < 8; nt++) {
                const uint2 B0 = Ws2[(nt * 8 + g) * SROW8 + kp];
                const uint2 B1 = Ws2[(nt * 8 + g) * SROW8 + kp + 4];
                MMA_BF16(C[0][nt], A0.x, A1.x, A2.x, A3.x, B0.x, B1.x);
                MMA_BF16(C[0][nt], A0.y, A1.y, A2.y, A3.y, B0.x, B1.x);
                MMA_BF16(C[0][nt], A0.x, A1.x, A2.x, A3.x, B0.y, B1.y);
                MMA_BF16(C[1][nt], D0.x, D1.x, D2.x, D3.x, B0.x, B1.x);
                MMA_BF16(C[1][nt], D0.y, D1.y, D2.y, D3.y, B0.x, B1.x);
                MMA_BF16(C[1][nt], D0.x, D1.x, D2.x, D3.x, B0.y, B1.y);
            }
        }
        __syncthreads();
    }

    // ---- epilogue: add (b+theta), write float2 pairs ----
    float2 bt2[8];
#pragma unroll
    for (int nt = 0; nt < 8; nt++)
        bt2[nt] = *(const float2*)&bts[nt * 8 + 2 * tig];

#pragma unroll
    for (int s = 0; s < 2; s++) {
        const size_t r0 = m0 + rb + 16 * s + g;
#pragma unroll
        for (int nt = 0; nt < 8; nt++) {
            const int col = nt * 8 + 2 * tig;
            *(float2*)&g_zx[r0 * GN + col] =
                make_float2(C[s][nt][0] + bt2[nt].x, C[s][nt][1] + bt2[nt].y);
            *(float2*)&g_zx[(r0 + 8) * GN + col] =
                make_float2(C[s][nt][2] + bt2[nt].x, C[s][nt][3] + bt2[nt].y);
        }
    }
}

// ===========================================================================
// Phase 2: recurrence, 32 lanes per batch element (1 warp = 1 element).
//   half0 owns gates {f(0), g(2)}; half1 owns {i(1), o(3)}.
//   qa -> sigmoid in both halves; qb -> tanh/sigmoid unified as
//   1 - b/(e^{s*qb}+1) with (s,b) = (2,2) / (1,1). Two xor-shfls give both
//   halves f,i,g,o -> (c,h) replicated identically in all 32 lanes.
// ===========================================================================
__device__ __forceinline__ float sigf(float x) {
    return __fdividef(1.0f, 1.0f + __expf(-x));
}
__device__ __forceinline__ float tanh_fast(float x) {
    return 1.0f - __fdividef(2.0f, __expf(2.0f * x) + 1.0f);
}
__device__ __forceinline__ float scanp(float p, int n) {
    float v1 = __shfl_up_sync(0xffffffffu, p, 1, 16);
    float v2 = __shfl_up_sync(0xffffffffu, p, 2, 16);
    float v3 = __shfl_up_sync(0xffffffffu, p, 3, 16);
    float m = ((n >= 1) ? v1 : 1.0f) * ((n >= 2) ? v2 : 1.0f);
    p *= m * ((n >= 3) ? v3 : 1.0f);
    float w1 = __shfl_up_sync(0xffffffffu, p, 4, 16);
    float w2 = __shfl_up_sync(0xffffffffu, p, 8, 16);
    float w3 = __shfl_up_sync(0xffffffffu, p, 12, 16);
    float mm = ((n >= 4) ? w1 : 1.0f) * ((n >= 8) ? w2 : 1.0f);
    return p * (mm * ((n >= 12) ? w3 : 1.0f));
}

__global__ __launch_bounds__(128) void qlstm_p2(
    const float* __restrict__ W, float* __restrict__ out, const int write_final)
{
    __shared__ float hs[2][4][16];

    const int tid  = threadIdx.x;
    const int lane = tid & 31;
    const int w    = tid >> 5;          // warp = element slot
    const int half = lane >> 4;
    const int n    = lane & 15;
    const int e    = blockIdx.x * 4 + w;

    // this lane's two gates: ga = half (f or i), gb = 2 + half (g or o)
    float Wa[16], Wb[16];
    {
        const float* wa = W + (size_t)(half * 16 + n) * 144 + 128;
        const float* wb = W + (size_t)((2 + half) * 16 + n) * 144 + 128;
#pragma unroll
        for (int j = 0; j < 16; j++) { Wa[j] = wa[j]; Wb[j] = wb[j]; }
    }

    float c = 0.0f, h = 0.0f;
    if (half == 0) hs[0][w][n] = 0.0f;
    __syncwarp();

    const size_t SS = (size_t)B_DIM * GN;
    const float* zpa = g_zx + (size_t)e * GN + half * 16 + n;
    const float* zpb = zpa + 32;
    float* outp = out + (size_t)e * NQ + n;

    const float sN = half ? 1.0f : 2.0f;   // qb act: half0 tanh, half1 sigmoid

    float zca[4], zcb[4];
#pragma unroll
    for (int s = 0; s < 4; s++) { zca[s] = zpa[s * SS]; zcb[s] = zpb[s * SS]; }
    zpa += 4 * SS; zpb += 4 * SS;

    for (int tb = 0; tb < 64; ++tb) {
        float zna[4], znb[4];
#pragma unroll
        for (int s = 0; s < 4; s++) { zna[s] = zpa[s * SS]; znb[s] = zpb[s * SS]; }
        zpa += 4 * SS; zpb += 4 * SS;

#pragma unroll
        for (int s = 0; s < 4; s++) {
            const int buf = s & 1;
            float hv[16];
            {
                const float4* hp = (const float4*)hs[buf][w];
#pragma unroll
                for (int q = 0; q < 4; q++) {
                    const float4 v = hp[q];
                    hv[4 * q + 0] = v.x; hv[4 * q + 1] = v.y;
                    hv[4 * q + 2] = v.z; hv[4 * q + 3] = v.w;
                }
            }
            float a0 = zca[s], a1 = 0.0f, a2 = 0.0f, a3 = 0.0f;
            float b0 = zcb[s], b1 = 0.0f, b2 = 0.0f, b3 = 0.0f;
#pragma unroll
            for (int j = 0; j < 4; j++) {
                a0 = fmaf(hv[j],      Wa[j],      a0);
                a1 = fmaf(hv[j + 4],  Wa[j + 4],  a1);
                a2 = fmaf(hv[j + 8],  Wa[j + 8],  a2);
                a3 = fmaf(hv[j + 12], Wa[j + 12], a3);
                b0 = fmaf(hv[j],      Wb[j],      b0);
                b1 = fmaf(hv[j + 4],  Wb[j + 4],  b1);
                b2 = fmaf(hv[j + 8],  Wb[j + 8],  b2);
                b3 = fmaf(hv[j + 12], Wb[j + 12], b3);
            }
            const float za = (a0 + a1) + (a2 + a3);
            const float zb = (b0 + b1) + (b2 + b3);

            const float qa = scanp(__cosf(za), n);
            const float qb = scanp(__cosf(zb), n);

            const float A = sigf(qa);                      // f (h0) / i (h1)
            const float v = 1.0f - sN * __fdividef(1.0f, __expf(sN * qb) + 1.0f);
            const float oA = __shfl_xor_sync(0xffffffffu, A, 16);
            const float oV = __shfl_xor_sync(0xffffffffu, v, 16);

            const float f  = half ? oA : A;
            const float ii = half ? A  : oA;
            const float gg = half ? oV : v;
            const float oo = half ? v  : oV;

            c = fmaf(f, c, ii * gg);
            h = oo * tanh_fast(c);

            if (half == 0) {
                outp[0] = h;
                hs[buf ^ 1][w][n] = h;
            }
            outp += B_DIM * NQ;
            __syncwarp();
        }
#pragma unroll
        for (int s = 0; s < 4; s++) { zca[s] = zna[s]; zcb[s] = znb[s]; }
    }

    if (write_final && half == 0) {
        float* hx = out + (size_t)T_DIM * B_DIM * NQ;
        hx[(size_t)e * NQ + n] = h;
        hx[(size_t)B_DIM * NQ + (size_t)e * NQ + n] = c;
    }
}

// ---------------------------------------------------------------------------
extern "C" void kernel_launch(void* const* d_in, const int* in_sizes, int n_in,
                              void* d_out, int out_size) {
    const float* X  = (const float*)d_in[0];
    const float* W  = (const float*)d_in[1];
    const float* Bb = (const float*)d_in[2];
    const float* Th = (const float*)d_in[3];
    float* out = (float*)d_out;

    cudaFuncSetAttribute(qlstm_p1, cudaFuncAttributeMaxDynamicSharedMemorySize,
                         P1_SMEM);
    qlstm_p1<<<M_TOT / 256, 256, P1_SMEM>>>(X, W, Bb, Th);

    const int need = T_DIM * B_DIM * NQ + 2 * B_DIM * NQ;
    const int wf = (out_size >= need) ? 1 : 0;
    qlstm_p2<<<B_DIM / 4, 128>>>(W, out, wf);
}